// round 2
// baseline (speedup 1.0000x reference)
#include <cuda_runtime.h>

#define B_SZ 512
#define D_SZ 1024
#define P_SZ 16
#define N_SZ 128
#define ALPHA_F 0.8f
#define NROWS 145            // row 0 = tgt, 1..16 = rel, 17..144 = irr
#define SPLIT 4
#define NBLOCKS (B_SZ * SPLIT)
#define TPB 128

__device__ float g_pos[NBLOCKS];
__device__ float g_neg[NBLOCKS];
__device__ float g_diag[B_SZ];
__device__ unsigned int g_count = 0;

__global__ void __launch_bounds__(TPB)
contrastive_loss_kernel(const float* __restrict__ src,
                        const float* __restrict__ tgt,
                        const float* __restrict__ rel,
                        const float* __restrict__ irr,
                        float* __restrict__ out)
{
    __shared__ float s_src[D_SZ];
    __shared__ float s_red[4];
    __shared__ float s_pos[4];
    __shared__ float s_neg[4];
    __shared__ float s_diag;
    __shared__ float s_inv;
    __shared__ int   s_last;

    const int blk  = blockIdx.x;
    const int b    = blk >> 2;          // batch row
    const int s    = blk & 3;           // split index
    const int tid  = threadIdx.x;
    const int wid  = tid >> 5;
    const int lane = tid & 31;

    // ---- load src row into shared; accumulate its sum of squares ----
    const float4* srcv = reinterpret_cast<const float4*>(src + (size_t)b * D_SZ);
    float ss = 0.f;
    #pragma unroll
    for (int i = 0; i < D_SZ / 4 / TPB; i++) {     // 2 iters
        int idx = i * TPB + tid;
        float4 v = srcv[idx];
        reinterpret_cast<float4*>(s_src)[idx] = v;
        ss += v.x * v.x + v.y * v.y + v.z * v.z + v.w * v.w;
    }
    #pragma unroll
    for (int o = 16; o > 0; o >>= 1) ss += __shfl_xor_sync(0xFFFFFFFFu, ss, o);
    if (lane == 0) s_red[wid] = ss;
    __syncthreads();
    if (tid == 0) {
        float t = s_red[0] + s_red[1] + s_red[2] + s_red[3];
        s_inv = rsqrtf(fmaxf(t, 1e-24f));          // 1/max(||src||,1e-12)
    }
    __syncthreads();
    const float inv_src = s_inv;

    // ---- this block's slice of the 145 rows ----
    const int r0 = (s * NROWS) / SPLIT;            // 0,36,72,108
    const int r1 = ((s + 1) * NROWS) / SPLIT;      // 36,72,108,145

    float pos_acc = 0.f, neg_acc = 0.f, diag = 0.f;

    for (int r = r0 + wid; r < r1; r += 4) {
        const float* row;
        if (r == 0)
            row = tgt + (size_t)b * D_SZ;
        else if (r <= P_SZ)
            row = rel + ((size_t)b * P_SZ + (r - 1)) * D_SZ;
        else
            row = irr + ((size_t)b * N_SZ + (r - 1 - P_SZ)) * D_SZ;

        const float4* rv = reinterpret_cast<const float4*>(row);
        float dot = 0.f, rss = 0.f;
        #pragma unroll
        for (int j = 0; j < 8; j++) {              // 8 LDG.128 in flight
            int idx = j * 32 + lane;
            float4 v  = rv[idx];
            float4 sv = reinterpret_cast<const float4*>(s_src)[idx];
            dot += v.x * sv.x + v.y * sv.y + v.z * sv.z + v.w * sv.w;
            rss += v.x * v.x + v.y * v.y + v.z * v.z + v.w * v.w;
        }
        #pragma unroll
        for (int o = 16; o > 0; o >>= 1) {
            dot += __shfl_xor_sync(0xFFFFFFFFu, dot, o);
            rss += __shfl_xor_sync(0xFFFFFFFFu, rss, o);
        }
        if (lane == 0) {
            float c = dot * inv_src * rsqrtf(fmaxf(rss, 1e-24f));
            if (r == 0)            diag = c;
            else if (r <= P_SZ)    pos_acc += expf(c);
            else                   neg_acc += expf(c);
        }
    }

    if (lane == 0) {
        s_pos[wid] = pos_acc;
        s_neg[wid] = neg_acc;
        if (wid == 0 && s == 0) s_diag = diag;
    }
    __syncthreads();

    if (tid == 0) {
        g_pos[blk] = s_pos[0] + s_pos[1] + s_pos[2] + s_pos[3];
        g_neg[blk] = s_neg[0] + s_neg[1] + s_neg[2] + s_neg[3];
        if (s == 0) g_diag[b] = s_diag;
        __threadfence();
        unsigned int old = atomicAdd(&g_count, 1u);
        s_last = (old == NBLOCKS - 1);
    }
    __syncthreads();

    // ---- last block computes the final loss (fused reduction) ----
    if (s_last) {
        float acc = 0.f;
        for (int bb = tid; bb < B_SZ; bb += TPB) {
            float ps = 0.f, ns = 0.f;
            #pragma unroll
            for (int k = 0; k < SPLIT; k++) {
                ps += g_pos[bb * SPLIT + k];
                ns += g_neg[bb * SPLIT + k];
            }
            float pos_score = 1.f + ps;
            float lp = logf(pos_score);
            float ln = logf(pos_score + ns);
            acc += -(ALPHA_F * g_diag[bb] + (1.f - ALPHA_F) * (lp - ln));
        }
        #pragma unroll
        for (int o = 16; o > 0; o >>= 1) acc += __shfl_xor_sync(0xFFFFFFFFu, acc, o);
        if (lane == 0) s_red[wid] = acc;
        __syncthreads();
        if (tid == 0) {
            out[0] = (s_red[0] + s_red[1] + s_red[2] + s_red[3]) * (1.0f / (float)B_SZ);
            g_count = 0;                // reset for the next graph replay
        }
    }
}

extern "C" void kernel_launch(void* const* d_in, const int* in_sizes, int n_in,
                              void* d_out, int out_size)
{
    const float* src = (const float*)d_in[0];   // [B, D]
    const float* tgt = (const float*)d_in[1];   // [B, D]
    const float* rel = (const float*)d_in[2];   // [B, P, D]
    const float* irr = (const float*)d_in[3];   // [B, N, D]
    float* out = (float*)d_out;

    contrastive_loss_kernel<<<NBLOCKS, TPB>>>(src, tgt, rel, irr, out);
}